// round 1
// baseline (speedup 1.0000x reference)
#include <cuda_runtime.h>
#include <cstdint>

#define T_STEPS 1024
#define BATCH   64
#define DIN     256
#define DH      256
#define G4      1024   // 4*DH
#define OUT_MAIN (T_STEPS*BATCH*DH)

// ---------------- scratch (static device globals; no allocation) ----------------
__device__ float g_Gx[(size_t)T_STEPS * BATCH * G4];   // 256 MB: precomputed x-part of gates
__device__ float g_WxT[DIN * G4];                      // Wx transposed [k][j], j = gate*256+h
__device__ float g_bvec[G4];                           // packed bias
__device__ float g_hbuf[2][BATCH * DH];                // double-buffered h
__device__ unsigned int g_bar[8 * 32];                 // per-batch-group barrier counters (padded)

// ---------------- barrier primitives ----------------
__device__ __forceinline__ void red_add_release(unsigned int* p) {
    unsigned int old;
    asm volatile("atom.add.release.gpu.u32 %0, [%1], 1;" : "=r"(old) : "l"(p) : "memory");
}
__device__ __forceinline__ unsigned int ld_acquire(const unsigned int* p) {
    unsigned int v;
    asm volatile("ld.acquire.gpu.u32 %0, [%1];" : "=r"(v) : "l"(p) : "memory");
    return v;
}

__device__ __forceinline__ float sigm(float x) { return 1.f / (1.f + __expf(-x)); }

// ---------------- prep: pack Wx (k-major) + bias ----------------
__global__ void prep_kernel(const float* __restrict__ Wf, const float* __restrict__ Wi,
                            const float* __restrict__ Wg, const float* __restrict__ Wo,
                            const float* __restrict__ bF, const float* __restrict__ bI,
                            const float* __restrict__ bG, const float* __restrict__ bO)
{
    int idx = blockIdx.x * blockDim.x + threadIdx.x;
    const float* Ws[4] = {Wf, Wi, Wg, Wo};
    for (int i = idx; i < DIN * G4; i += gridDim.x * blockDim.x) {
        int k = i >> 10;          // 0..255
        int j = i & (G4 - 1);     // 0..1023
        int gate = j >> 8;
        int row  = j & 255;
        g_WxT[i] = Ws[gate][row * 512 + k];   // x-part is first 256 cols of W
    }
    if (idx < G4) {
        int gate = idx >> 8, row = idx & 255;
        const float* bs[4] = {bF, bI, bG, bO};
        g_bvec[idx] = bs[gate][row];
    }
}

// ---------------- init: h0 -> buffer, reset barriers (every graph replay) ----------------
__global__ void init_kernel(const float* __restrict__ h0)
{
    int i = blockIdx.x * blockDim.x + threadIdx.x;
    if (i < BATCH * DH) g_hbuf[0][i] = h0[i];
    if (i < 8 * 32)     g_bar[i] = 0;
}

// ---------------- phase 1: Gx = X @ Wx^T + b   (65536 x 1024 x 256 SGEMM) ----------------
__global__ __launch_bounds__(256) void gemm_x_kernel(const float* __restrict__ A)
{
    __shared__ float As[8][128];
    __shared__ float Bs[8][128];

    int tid = threadIdx.x;
    int bn = blockIdx.x;   // 0..7   (N/128)
    int bm = blockIdx.y;   // 0..511 (M/128)
    int tx = tid & 15;
    int ty = tid >> 4;

    float acc[8][8];
    #pragma unroll
    for (int i = 0; i < 8; i++)
        #pragma unroll
        for (int j = 0; j < 8; j++) acc[i][j] = 0.f;

    const float* Aptr = A + (size_t)bm * 128 * DIN;
    const float* Bptr = g_WxT + bn * 128;

    int arow = tid >> 1;
    int acol = (tid & 1) << 2;
    int bkk  = tid >> 5;
    int bj   = (tid & 31) << 2;

    for (int k0 = 0; k0 < DIN; k0 += 8) {
        float4 a4 = *(const float4*)(Aptr + arow * DIN + k0 + acol);
        As[acol + 0][arow] = a4.x;
        As[acol + 1][arow] = a4.y;
        As[acol + 2][arow] = a4.z;
        As[acol + 3][arow] = a4.w;
        *(float4*)&Bs[bkk][bj] = *(const float4*)(Bptr + (size_t)(k0 + bkk) * G4 + bj);
        __syncthreads();

        #pragma unroll
        for (int kk = 0; kk < 8; kk++) {
            float4 a0 = *(const float4*)&As[kk][ty * 8];
            float4 a1 = *(const float4*)&As[kk][ty * 8 + 4];
            float4 b0 = *(const float4*)&Bs[kk][tx * 8];
            float4 b1 = *(const float4*)&Bs[kk][tx * 8 + 4];
            float af[8] = {a0.x, a0.y, a0.z, a0.w, a1.x, a1.y, a1.z, a1.w};
            float bf[8] = {b0.x, b0.y, b0.z, b0.w, b1.x, b1.y, b1.z, b1.w};
            #pragma unroll
            for (int mi = 0; mi < 8; mi++)
                #pragma unroll
                for (int ni = 0; ni < 8; ni++)
                    acc[mi][ni] += af[mi] * bf[ni];
        }
        __syncthreads();
    }

    int jbase = bn * 128 + tx * 8;
    float4 bb0 = *(const float4*)&g_bvec[jbase];
    float4 bb1 = *(const float4*)&g_bvec[jbase + 4];
    #pragma unroll
    for (int mi = 0; mi < 8; mi++) {
        size_t r = (size_t)bm * 128 + ty * 8 + mi;
        float* op = g_Gx + r * G4 + jbase;
        float4 o0 = make_float4(acc[mi][0] + bb0.x, acc[mi][1] + bb0.y,
                                acc[mi][2] + bb0.z, acc[mi][3] + bb0.w);
        float4 o1 = make_float4(acc[mi][4] + bb1.x, acc[mi][5] + bb1.y,
                                acc[mi][6] + bb1.z, acc[mi][7] + bb1.w);
        *(float4*)op = o0;
        *(float4*)(op + 4) = o1;
    }
}

// ---------------- phase 2: persistent recurrent kernel ----------------
// 128 CTAs = 8 batch-groups (8 batches each) x 16 H-slices (16 h each, x4 gates = 64 cols).
// Wh slice lives in registers (64 floats/thread). Sync only within a batch-group (16 CTAs).
__global__ __launch_bounds__(256, 1) void lstm_kernel(
    const float* __restrict__ Wf, const float* __restrict__ Wi,
    const float* __restrict__ Wg, const float* __restrict__ Wo,
    const float* __restrict__ c0, float* __restrict__ out, int out_size)
{
    __shared__ float4 sh_h4[8 * 64];        // h slice [8 batches][256] as float4
    __shared__ float  sh_part[64 * 144];    // partials [pair][kg][batch], pad 8->9
    __shared__ float  sh_gates[512];        // reduced gates, idx = pair*8 + batch

    int tid = threadIdx.x;
    int bg = blockIdx.x >> 4;   // batch group 0..7
    int cg = blockIdx.x & 15;   // h-slice 0..15
    int pg = tid >> 4;          // pair group 0..15
    int kg = tid & 15;          // k group 0..15
    int gate = pg >> 2;

    const float* Wsel = (gate == 0) ? Wf : (gate == 1) ? Wi : (gate == 2) ? Wg : Wo;

    // Load Wh slice into registers. Thread owns 4 pairs (gate fixed, 4 consecutive h)
    // and k-set {kg*4 + c*64 + x : c in 0..3, x in 0..3} (keeps smem h reads conflict-free).
    float wreg[4][16];
    #pragma unroll
    for (int q = 0; q < 4; q++) {
        int hh = ((pg & 3) << 2) + q;
        int hglob = cg * 16 + hh;
        const float* wp = Wsel + hglob * 512 + 256;   // h-part = last 256 cols
        #pragma unroll
        for (int c = 0; c < 4; c++) {
            float4 w4 = *(const float4*)(wp + kg * 4 + c * 64);
            wreg[q][c * 4 + 0] = w4.x;
            wreg[q][c * 4 + 1] = w4.y;
            wreg[q][c * 4 + 2] = w4.z;
            wreg[q][c * 4 + 3] = w4.w;
        }
    }

    // cell state ownership: tid<128 holds c for (batch b_loc, h hh_c)
    int b_loc = tid >> 4;
    int hh_c  = tid & 15;
    int brow  = bg * 8 + b_loc;
    int colg  = cg * 16 + hh_c;
    float cval = (tid < 128) ? c0[brow * DH + colg] : 0.f;

    // Gx gather offsets for this thread's 2 outputs (o = tid and tid+256)
    int p0 = tid >> 3, b0 = tid & 7;
    int p1 = (tid + 256) >> 3, b1 = tid & 7;
    size_t gx_off0 = (size_t)(bg * 8 + b0) * G4 + ((p0 >> 4) * 256 + cg * 16 + (p0 & 15));
    size_t gx_off1 = (size_t)(bg * 8 + b1) * G4 + ((p1 >> 4) * 256 + cg * 16 + (p1 & 15));

    unsigned int* barp = &g_bar[bg * 32];
    const size_t hbase4 = (size_t)bg * 8 * DH / 4;

    #pragma unroll 1
    for (int t = 0; t < T_STEPS; t++) {
        // prefetch the x-part gate contributions for this step (DRAM latency hidden by compute)
        size_t gxt = (size_t)t * (BATCH * G4);
        float gx0 = g_Gx[gxt + gx_off0];
        float gx1 = g_Gx[gxt + gx_off1];

        // stage h slice into smem
        const float4* hsrc = (const float4*)g_hbuf[t & 1] + hbase4;
        sh_h4[tid]       = hsrc[tid];
        sh_h4[tid + 256] = hsrc[tid + 256];
        __syncthreads();

        // partial dot products: 512 FMA / thread
        float acc[4][8];
        #pragma unroll
        for (int q = 0; q < 4; q++)
            #pragma unroll
            for (int b = 0; b < 8; b++) acc[q][b] = 0.f;

        #pragma unroll
        for (int c = 0; c < 4; c++) {
            #pragma unroll
            for (int b = 0; b < 8; b++) {
                float4 h4 = sh_h4[b * 64 + c * 16 + kg];
                #pragma unroll
                for (int q = 0; q < 4; q++) {
                    acc[q][b] += wreg[q][c * 4 + 0] * h4.x;
                    acc[q][b] += wreg[q][c * 4 + 1] * h4.y;
                    acc[q][b] += wreg[q][c * 4 + 2] * h4.z;
                    acc[q][b] += wreg[q][c * 4 + 3] * h4.w;
                }
            }
        }

        // stage A: spill partials to smem
        #pragma unroll
        for (int q = 0; q < 4; q++) {
            int p = pg * 4 + q;
            float* dst = &sh_part[p * 144 + kg * 9];
            #pragma unroll
            for (int b = 0; b < 8; b++) dst[b] = acc[q][b];
        }
        __syncthreads();

        // stage B: reduce over 16 k-groups + add Gx
        float s0 = gx0, s1 = gx1;
        #pragma unroll
        for (int k2 = 0; k2 < 16; k2++) s0 += sh_part[p0 * 144 + k2 * 9 + b0];
        #pragma unroll
        for (int k2 = 0; k2 < 16; k2++) s1 += sh_part[p1 * 144 + k2 * 9 + b1];
        sh_gates[tid]       = s0;
        sh_gates[tid + 256] = s1;
        __syncthreads();

        // stage C: LSTM cell update (tid<128 handles one (b,h))
        if (tid < 128) {
            float fg = sigm(sh_gates[        hh_c * 8 + b_loc]);
            float ig = sigm(sh_gates[128 +   hh_c * 8 + b_loc]);
            float gg = tanhf(sh_gates[256 +  hh_c * 8 + b_loc]);
            float og = sigm(sh_gates[384 +   hh_c * 8 + b_loc]);
            cval = fg * cval + ig * gg;
            float hn = og * tanhf(cval);
            g_hbuf[(t + 1) & 1][brow * DH + colg] = hn;
            out[(size_t)t * (BATCH * DH) + brow * DH + colg] = hn;
            if (t == T_STEPS - 1 && out_size > OUT_MAIN) {
                out[(size_t)OUT_MAIN + brow * DH + colg] = hn;
                out[(size_t)OUT_MAIN + BATCH * DH + brow * DH + colg] = cval;
            }
        }
        __syncthreads();

        // batch-group barrier (16 CTAs, release/acquire on own counter)
        if (tid == 0) {
            red_add_release(barp);
            unsigned int target = 16u * (unsigned)(t + 1);
            while (ld_acquire(barp) < target) { }
        }
        __syncthreads();
    }
}

// ---------------- launch ----------------
extern "C" void kernel_launch(void* const* d_in, const int* in_sizes, int n_in,
                              void* d_out, int out_size)
{
    const float* inputs = (const float*)d_in[0];
    const float* h0     = (const float*)d_in[1];
    const float* c0     = (const float*)d_in[2];
    const float* Wf     = (const float*)d_in[3];
    const float* bF     = (const float*)d_in[4];
    const float* Wi     = (const float*)d_in[5];
    const float* bI     = (const float*)d_in[6];
    const float* Wg     = (const float*)d_in[7];
    const float* bG     = (const float*)d_in[8];
    const float* Wo     = (const float*)d_in[9];
    const float* bO     = (const float*)d_in[10];
    float* out = (float*)d_out;

    prep_kernel<<<256, 256>>>(Wf, Wi, Wg, Wo, bF, bI, bG, bO);
    init_kernel<<<64, 256>>>(h0);
    gemm_x_kernel<<<dim3(8, 512), 256>>>(inputs);
    lstm_kernel<<<128, 256>>>(Wf, Wi, Wg, Wo, c0, out, out_size);
}

// round 2
// speedup vs baseline: 1.0367x; 1.0367x over previous
#include <cuda_runtime.h>
#include <cstdint>

#define T_STEPS 1024
#define BATCH   64
#define DIN     256
#define DH      256
#define G4      1024   // 4*DH
#define OUT_MAIN (T_STEPS*BATCH*DH)

// ---------------- scratch (static device globals; no allocation) ----------------
__device__ float g_Gx[(size_t)T_STEPS * BATCH * G4];   // 256 MB: precomputed x-part of gates
__device__ float g_WxT[DIN * G4];                      // Wx transposed [k][j], j = gate*256+h
__device__ float g_bvec[G4];                           // packed bias
__device__ float g_hbuf[2][BATCH * DH];                // double-buffered h
__device__ unsigned int g_flags[16 * 16];              // per-group: 8 producer flags (padded rows)

// ---------------- sync primitives ----------------
__device__ __forceinline__ void st_release(unsigned int* p, unsigned int v) {
    asm volatile("st.release.gpu.u32 [%0], %1;" :: "l"(p), "r"(v) : "memory");
}
__device__ __forceinline__ unsigned int ld_acquire(const unsigned int* p) {
    unsigned int v;
    asm volatile("ld.acquire.gpu.u32 %0, [%1];" : "=r"(v) : "l"(p) : "memory");
    return v;
}
__device__ __forceinline__ float4 ldcg4(const float4* p) {
    float4 v;
    asm volatile("ld.global.cg.v4.f32 {%0,%1,%2,%3}, [%4];"
                 : "=f"(v.x), "=f"(v.y), "=f"(v.z), "=f"(v.w) : "l"(p) : "memory");
    return v;
}

__device__ __forceinline__ float sigm(float x) { return 1.f / (1.f + __expf(-x)); }
__device__ __forceinline__ float tanh_fast(float x) {
    float e = __expf(2.f * x);
    return (e - 1.f) * __frcp_rn(e + 1.f);
}

// ---------------- prep: pack Wx (k-major) + bias ----------------
__global__ void prep_kernel(const float* __restrict__ Wf, const float* __restrict__ Wi,
                            const float* __restrict__ Wg, const float* __restrict__ Wo,
                            const float* __restrict__ bF, const float* __restrict__ bI,
                            const float* __restrict__ bG, const float* __restrict__ bO)
{
    int idx = blockIdx.x * blockDim.x + threadIdx.x;
    const float* Ws[4] = {Wf, Wi, Wg, Wo};
    for (int i = idx; i < DIN * G4; i += gridDim.x * blockDim.x) {
        int k = i >> 10;          // 0..255
        int j = i & (G4 - 1);     // 0..1023
        int gate = j >> 8;
        int row  = j & 255;
        g_WxT[i] = Ws[gate][row * 512 + k];   // x-part is first 256 cols of W
    }
    if (idx < G4) {
        int gate = idx >> 8, row = idx & 255;
        const float* bs[4] = {bF, bI, bG, bO};
        g_bvec[idx] = bs[gate][row];
    }
}

// ---------------- init: h0 -> buffer, reset flags (every graph replay) ----------------
__global__ void init_kernel(const float* __restrict__ h0)
{
    int i = blockIdx.x * blockDim.x + threadIdx.x;
    if (i < BATCH * DH) g_hbuf[0][i] = h0[i];
    if (i < 16 * 16)    g_flags[i] = 0;
}

// ---------------- phase 1: Gx = X @ Wx^T + b   (65536 x 1024 x 256 SGEMM) ----------------
__global__ __launch_bounds__(256) void gemm_x_kernel(const float* __restrict__ A)
{
    __shared__ float As[8][128];
    __shared__ float Bs[8][128];

    int tid = threadIdx.x;
    int bn = blockIdx.x;   // 0..7   (N/128)
    int bm = blockIdx.y;   // 0..511 (M/128)
    int tx = tid & 15;
    int ty = tid >> 4;

    float acc[8][8];
    #pragma unroll
    for (int i = 0; i < 8; i++)
        #pragma unroll
        for (int j = 0; j < 8; j++) acc[i][j] = 0.f;

    const float* Aptr = A + (size_t)bm * 128 * DIN;
    const float* Bptr = g_WxT + bn * 128;

    int arow = tid >> 1;
    int acol = (tid & 1) << 2;
    int bkk  = tid >> 5;
    int bj   = (tid & 31) << 2;

    for (int k0 = 0; k0 < DIN; k0 += 8) {
        float4 a4 = *(const float4*)(Aptr + arow * DIN + k0 + acol);
        As[acol + 0][arow] = a4.x;
        As[acol + 1][arow] = a4.y;
        As[acol + 2][arow] = a4.z;
        As[acol + 3][arow] = a4.w;
        *(float4*)&Bs[bkk][bj] = *(const float4*)(Bptr + (size_t)(k0 + bkk) * G4 + bj);
        __syncthreads();

        #pragma unroll
        for (int kk = 0; kk < 8; kk++) {
            float4 a0 = *(const float4*)&As[kk][ty * 8];
            float4 a1 = *(const float4*)&As[kk][ty * 8 + 4];
            float4 b0 = *(const float4*)&Bs[kk][tx * 8];
            float4 b1 = *(const float4*)&Bs[kk][tx * 8 + 4];
            float af[8] = {a0.x, a0.y, a0.z, a0.w, a1.x, a1.y, a1.z, a1.w};
            float bf[8] = {b0.x, b0.y, b0.z, b0.w, b1.x, b1.y, b1.z, b1.w};
            #pragma unroll
            for (int mi = 0; mi < 8; mi++)
                #pragma unroll
                for (int ni = 0; ni < 8; ni++)
                    acc[mi][ni] += af[mi] * bf[ni];
        }
        __syncthreads();
    }

    int jbase = bn * 128 + tx * 8;
    float4 bb0 = *(const float4*)&g_bvec[jbase];
    float4 bb1 = *(const float4*)&g_bvec[jbase + 4];
    #pragma unroll
    for (int mi = 0; mi < 8; mi++) {
        size_t r = (size_t)bm * 128 + ty * 8 + mi;
        float* op = g_Gx + r * G4 + jbase;
        float4 o0 = make_float4(acc[mi][0] + bb0.x, acc[mi][1] + bb0.y,
                                acc[mi][2] + bb0.z, acc[mi][3] + bb0.w);
        float4 o1 = make_float4(acc[mi][4] + bb1.x, acc[mi][5] + bb1.y,
                                acc[mi][6] + bb1.z, acc[mi][7] + bb1.w);
        *(float4*)op = o0;
        *(float4*)(op + 4) = o1;
    }
}

// ---------------- phase 2: persistent recurrent kernel ----------------
// 128 CTAs = 16 batch-groups (4 batches) x 8 h-slices (32 h cols, all 4 gates).
// Thread: hh = tid>>3 (h col within slice), kg = tid&7 (k-chunk set, strided chunks).
// Weights Wh[4 gates][32 k] in registers (128 floats). Reduction over kg via shfl.bfly.
// Lane kg<4 then owns the cell for batch kg at column hh: no smem gate exchange.
__global__ __launch_bounds__(256, 1) void lstm_kernel(
    const float* __restrict__ Wf, const float* __restrict__ Wi,
    const float* __restrict__ Wg, const float* __restrict__ Wo,
    const float* __restrict__ c0, float* __restrict__ out, int out_size)
{
    __shared__ float4 sh_h4[4 * 64];   // h slice: [4 batches][256 floats] as float4

    int tid = threadIdx.x;
    int grp = blockIdx.x >> 3;    // 0..15 batch group (4 batches)
    int cg  = blockIdx.x & 7;     // 0..7  h-slice (32 h cols)
    int hh  = tid >> 3;           // 0..31
    int kg  = tid & 7;            // 0..7

    int hglob = cg * 32 + hh;
    const float* Wp[4] = {Wf + hglob * 512 + 256, Wi + hglob * 512 + 256,
                          Wg + hglob * 512 + 256, Wo + hglob * 512 + 256};

    // weights: k-chunks j = c*8 + kg (strided), chunk = 4 floats
    float4 w4[4][8];
    #pragma unroll
    for (int g = 0; g < 4; g++)
        #pragma unroll
        for (int c = 0; c < 8; c++)
            w4[g][c] = *(const float4*)(Wp[g] + (c * 8 + kg) * 4);

    // cell ownership: lanes kg<4 hold cell (batch kg, col hglob)
    int bglob = grp * 4 + kg;     // valid when kg < 4
    float cval = (kg < 4) ? c0[bglob * DH + hglob] : 0.f;

    unsigned int* flags = &g_flags[grp * 16];
    const size_t hoff = (size_t)grp * 4 * DH;   // this group's h slice offset (floats)

    #pragma unroll 1
    for (int t = 0; t < T_STEPS; t++) {
        // prefetch Gx for this step (independent of flags; hides DRAM latency)
        float gx[4];
        if (kg < 4) {
            const float* gp = g_Gx + (size_t)t * (BATCH * G4) + (size_t)bglob * G4 + hglob;
            #pragma unroll
            for (int g = 0; g < 4; g++) gx[g] = gp[g * 256];
        }

        // wait for all 8 producers of this group to publish h[t]
        if (tid < 8) {
            while (ld_acquire(&flags[tid]) < (unsigned)t) { }
        }
        __syncthreads();

        // stage h[t] (4 batches x 256) into smem; .cg bypasses stale L1
        const float4* hsrc = (const float4*)(g_hbuf[t & 1] + hoff);
        sh_h4[tid] = ldcg4(hsrc + tid);
        __syncthreads();

        // partial dots: acc[gate][batch] over this thread's 32 k's
        float acc[4][4];
        #pragma unroll
        for (int g = 0; g < 4; g++)
            #pragma unroll
            for (int b = 0; b < 4; b++) acc[g][b] = 0.f;

        #pragma unroll
        for (int c = 0; c < 8; c++) {
            #pragma unroll
            for (int b = 0; b < 4; b++) {
                float4 h4 = sh_h4[b * 64 + c * 8 + kg];
                #pragma unroll
                for (int g = 0; g < 4; g++) {
                    acc[g][b] += w4[g][c].x * h4.x;
                    acc[g][b] += w4[g][c].y * h4.y;
                    acc[g][b] += w4[g][c].z * h4.z;
                    acc[g][b] += w4[g][c].w * h4.w;
                }
            }
        }

        // butterfly reduce over kg (lane bits 0..2)
        #pragma unroll
        for (int m = 1; m < 8; m <<= 1) {
            #pragma unroll
            for (int g = 0; g < 4; g++)
                #pragma unroll
                for (int b = 0; b < 4; b++)
                    acc[g][b] += __shfl_xor_sync(0xffffffffu, acc[g][b], m);
        }

        // cell update: lane kg<4 handles batch kg
        if (kg < 4) {
            float fg = sigm(acc[0][kg] + gx[0]);
            float ig = sigm(acc[1][kg] + gx[1]);
            float gg = tanh_fast(acc[2][kg] + gx[2]);
            float og = sigm(acc[3][kg] + gx[3]);
            cval = fg * cval + ig * gg;
            float hn = og * tanh_fast(cval);
            int idx = bglob * DH + hglob;
            g_hbuf[(t + 1) & 1][idx] = hn;
            out[(size_t)t * (BATCH * DH) + idx] = hn;
            if (t == T_STEPS - 1 && out_size > OUT_MAIN) {
                out[(size_t)OUT_MAIN + idx] = hn;
                out[(size_t)OUT_MAIN + BATCH * DH + idx] = cval;
            }
        }
        __syncthreads();

        // publish: all this CTA's h stores are ordered before the flag via bar + release
        if (tid == 0) st_release(&flags[cg], (unsigned)(t + 1));
    }
}

// ---------------- launch ----------------
extern "C" void kernel_launch(void* const* d_in, const int* in_sizes, int n_in,
                              void* d_out, int out_size)
{
    const float* inputs = (const float*)d_in[0];
    const float* h0     = (const float*)d_in[1];
    const float* c0     = (const float*)d_in[2];
    const float* Wf     = (const float*)d_in[3];
    const float* bF     = (const float*)d_in[4];
    const float* Wi     = (const float*)d_in[5];
    const float* bI     = (const float*)d_in[6];
    const float* Wg     = (const float*)d_in[7];
    const float* bG     = (const float*)d_in[8];
    const float* Wo     = (const float*)d_in[9];
    const float* bO     = (const float*)d_in[10];
    float* out = (float*)d_out;

    prep_kernel<<<256, 256>>>(Wf, Wi, Wg, Wo, bF, bI, bG, bO);
    init_kernel<<<64, 256>>>(h0);
    gemm_x_kernel<<<dim3(8, 512), 256>>>(inputs);
    lstm_kernel<<<128, 256>>>(Wf, Wi, Wg, Wo, c0, out, out_size);
}